// round 1
// baseline (speedup 1.0000x reference)
#include <cuda_runtime.h>
#include <math.h>

#define BN 8192
#define NN 100000
#define DD 8
#define KK 32
#define CC 100
#define TOTAL (BN + NN)

// Feature scratch: [0..BN) = transformed queries qx, [BN..TOTAL) = transformed nodes nx.
// Stored as interleaved (x,y) float pairs for float2 gathers.
__device__ float g_feat[TOTAL * 2];

// ---------------- shared-memory layout for mlp_kernel (float offsets) ----------------
// W2t  : [k=100][j=100] transposed W2                    -> 10000 floats @ 0       (16B aligned)
// W3t  : [k=100][j=32]  transposed W3, rows padded to 32 ->  3200 floats @ 10000   (16B aligned)
// W1s  : [j=100][2]                                      ->   200 floats @ 13200
// b1s  : 100 @ 13400 ; b2s : 100 @ 13500 ; b3s : 32 @ 13600
// W4s  : [o=2][32 padded] -> 64 @ 13632 ; b4s : 4 @ 13696
// h    : [100][128] per-thread activation columns        -> 12800 floats @ 13700   (16B aligned)
#define OFF_W2T 0
#define OFF_W3T 10000
#define OFF_W1  13200
#define OFF_B1  13400
#define OFF_B2  13500
#define OFF_B3  13600
#define OFF_W4  13632
#define OFF_B4  13696
#define OFF_H   13700
#define SMEM_FLOATS (OFF_H + 100 * 128)   // 26500 floats = 106000 bytes

__global__ __launch_bounds__(128)
void mlp_kernel(const float* __restrict__ x, const float* __restrict__ nd,
                const float* __restrict__ W1, const float* __restrict__ b1,
                const float* __restrict__ W2, const float* __restrict__ b2,
                const float* __restrict__ W3, const float* __restrict__ b3,
                const float* __restrict__ W4, const float* __restrict__ b4)
{
    extern __shared__ float sm[];
    const int tid = threadIdx.x;

    // ---- stage weights into shared (transpose W2, W3 so output index j is contiguous) ----
    for (int i = tid; i < 10000; i += 128) {
        int j = i / 100, k = i - j * 100;          // W2[j][k]
        sm[OFF_W2T + k * 100 + j] = W2[i];
    }
    for (int i = tid; i < 3000; i += 128) {
        int j = i / 100, k = i - j * 100;          // W3[j][k]
        sm[OFF_W3T + k * 32 + j] = W3[i];
    }
    for (int i = tid; i < 200; i += 128) sm[OFF_W1 + i] = W1[i];
    if (tid < 100) { sm[OFF_B1 + tid] = b1[tid]; sm[OFF_B2 + tid] = b2[tid]; }
    if (tid < 32)  sm[OFF_B3 + tid] = (tid < 30) ? b3[tid] : 0.f;
    if (tid < 64)  sm[OFF_W4 + (tid / 32) * 32 + (tid % 32)] =
                       ((tid % 32) < 30) ? W4[(tid / 32) * 30 + (tid % 32)] : 0.f;
    if (tid < 2)   sm[OFF_B4 + tid] = b4[tid];
    __syncthreads();

    const int p = blockIdx.x * 128 + tid;
    float px = 0.f, py = 0.f;
    if (p < TOTAL) {
        const float2 v = (p < BN) ? ((const float2*)x)[p] : ((const float2*)nd)[p - BN];
        px = v.x; py = v.y;
    }

    float* h = sm + OFF_H;   // this thread owns column `tid` — no cross-thread sharing, no syncs

    // ---- layer 1: 2 -> 100, ReLU ----
    for (int j = 0; j < 100; j++) {
        float v = fmaf(sm[OFF_W1 + 2 * j], px,
                  fmaf(sm[OFF_W1 + 2 * j + 1], py, sm[OFF_B1 + j]));
        h[j * 128 + tid] = fmaxf(v, 0.f);
    }

    // ---- layer 2: 100 -> 100, ReLU.  acc in registers, h1 streamed from smem. ----
    float acc[100];
    {
        const float4* b2v = (const float4*)(sm + OFF_B2);
        #pragma unroll
        for (int j4 = 0; j4 < 25; j4++) {
            float4 b = b2v[j4];
            acc[4 * j4 + 0] = b.x; acc[4 * j4 + 1] = b.y;
            acc[4 * j4 + 2] = b.z; acc[4 * j4 + 3] = b.w;
        }
    }
    const float4* W2t4 = (const float4*)(sm + OFF_W2T);
    for (int k = 0; k < 100; k++) {
        const float hk = h[k * 128 + tid];
        #pragma unroll
        for (int j4 = 0; j4 < 25; j4++) {
            float4 w = W2t4[k * 25 + j4];
            acc[4 * j4 + 0] = fmaf(w.x, hk, acc[4 * j4 + 0]);
            acc[4 * j4 + 1] = fmaf(w.y, hk, acc[4 * j4 + 1]);
            acc[4 * j4 + 2] = fmaf(w.z, hk, acc[4 * j4 + 2]);
            acc[4 * j4 + 3] = fmaf(w.w, hk, acc[4 * j4 + 3]);
        }
    }
    #pragma unroll
    for (int j = 0; j < 100; j++) h[j * 128 + tid] = fmaxf(acc[j], 0.f);

    // ---- layer 3: 100 -> 30, ReLU applied when consumed ----
    float h3[30];
    #pragma unroll
    for (int j = 0; j < 30; j++) h3[j] = sm[OFF_B3 + j];
    const float4* W3t4 = (const float4*)(sm + OFF_W3T);
    const float2* W3t2 = (const float2*)(sm + OFF_W3T);
    for (int k = 0; k < 100; k++) {
        const float hk = h[k * 128 + tid];
        #pragma unroll
        for (int j4 = 0; j4 < 7; j4++) {
            float4 w = W3t4[k * 8 + j4];
            h3[4 * j4 + 0] = fmaf(w.x, hk, h3[4 * j4 + 0]);
            h3[4 * j4 + 1] = fmaf(w.y, hk, h3[4 * j4 + 1]);
            h3[4 * j4 + 2] = fmaf(w.z, hk, h3[4 * j4 + 2]);
            h3[4 * j4 + 3] = fmaf(w.w, hk, h3[4 * j4 + 3]);
        }
        float2 w2 = W3t2[k * 16 + 14];
        h3[28] = fmaf(w2.x, hk, h3[28]);
        h3[29] = fmaf(w2.y, hk, h3[29]);
    }

    // ---- layer 4: 30 -> 2, linear ----
    float o0 = sm[OFF_B4 + 0], o1 = sm[OFF_B4 + 1];
    #pragma unroll
    for (int j = 0; j < 30; j++) {
        float r = fmaxf(h3[j], 0.f);
        o0 = fmaf(sm[OFF_W4 + j], r, o0);
        o1 = fmaf(sm[OFF_W4 + 32 + j], r, o1);
    }

    if (p < TOTAL) ((float2*)g_feat)[p] = make_float2(o0, o1);
}

// ---------------- routing kernel: one block per query b ----------------
// warp d in [0,8) handles path step d, lane k in [0,32) handles neighbor k.
__global__ __launch_bounds__(256)
void route_kernel(const int* __restrict__ nbr_idx, const int* __restrict__ labels,
                  float* __restrict__ out)
{
    __shared__ float p_s[CC];
    __shared__ float terms[DD - 1];

    const int b = blockIdx.x;
    const int tid = threadIdx.x;
    const int d = tid >> 5, lane = tid & 31;

    if (tid < CC) p_s[tid] = 0.f;
    __syncthreads();

    const float2 q = ((const float2*)g_feat)[b];
    const int idx = nbr_idx[b * (DD * KK) + tid];    // coalesced: [B][D][K]
    const float2 g = ((const float2*)g_feat)[BN + idx];

    const float dx = g.x - q.x + 1e-6f;              // F.pairwise_distance eps on the diff
    const float dy = g.y - q.y + 1e-6f;
    const float neg = -sqrtf(fmaf(dx, dx, dy * dy));

    float m = neg;
    #pragma unroll
    for (int o = 16; o > 0; o >>= 1) m = fmaxf(m, __shfl_xor_sync(0xffffffffu, m, o));
    const float e = expf(neg - m);
    float s = e;
    #pragma unroll
    for (int o = 16; o > 0; o >>= 1) s += __shfl_xor_sync(0xffffffffu, s, o);

    if (d < DD - 1) {
        // max_k softmax == exp(0)/s == 1/s exactly (argmax lane has neg-m == 0.0f)
        if (lane == 0) terms[d] = logf(1.0f / s + 1e-4f);
    } else {
        // final step: p[c] += sm_k for each neighbor's label c  (einsum vs one-hot)
        const int c = labels[idx];
        atomicAdd(&p_s[c], e / s);
    }
    __syncthreads();

    if (tid < CC) {
        float t = terms[0] + terms[1] + terms[2] + terms[3] + terms[4] + terms[5] + terms[6];
        out[(long)b * CC + tid] = logf(p_s[tid] + 1e-4f) + t;
    }
}

extern "C" void kernel_launch(void* const* d_in, const int* in_sizes, int n_in,
                              void* d_out, int out_size)
{
    const float* x      = (const float*)d_in[0];
    const float* nd     = (const float*)d_in[1];
    const float* W1     = (const float*)d_in[2];
    const float* b1     = (const float*)d_in[3];
    const float* W2     = (const float*)d_in[4];
    const float* b2     = (const float*)d_in[5];
    const float* W3     = (const float*)d_in[6];
    const float* b3     = (const float*)d_in[7];
    const float* W4     = (const float*)d_in[8];
    const float* b4     = (const float*)d_in[9];
    const int*   labels = (const int*)d_in[10];
    const int*   nbr    = (const int*)d_in[11];
    float* out = (float*)d_out;

    cudaFuncSetAttribute(mlp_kernel, cudaFuncAttributeMaxDynamicSharedMemorySize,
                         SMEM_FLOATS * (int)sizeof(float));

    const int blocks = (TOTAL + 127) / 128;
    mlp_kernel<<<blocks, 128, SMEM_FLOATS * sizeof(float)>>>(
        x, nd, W1, b1, W2, b2, W3, b3, W4, b4);
    route_kernel<<<BN, 256>>>(nbr, labels, out);
}

// round 3
// speedup vs baseline: 1.0611x; 1.0611x over previous
#include <cuda_runtime.h>
#include <math.h>

#define BN 8192
#define NN 100000
#define DD 8
#define KK 32
#define CC 100
#define TOTAL (BN + NN)

// Feature scratch: [0..BN) = transformed queries qx, [BN..TOTAL) = transformed nodes nx.
__device__ float g_feat[TOTAL * 2];

// ---------------- shared-memory layout for mlp_kernel (float offsets) ----------------
#define OFF_W2T 0          // [k=100][j=100] transposed W2     (10000 floats, 16B aligned)
#define OFF_W3T 10000      // [k=100][j=32] transposed W3 pad  (3200 floats, 40000B: 16B aligned)
#define OFF_W1  13200      // [j=100][2]                       (200 floats)
#define OFF_B1  13400      // 100
#define OFF_B2  13500      // 100 (54000B: 8B aligned)
#define OFF_B3  13600      // 32 padded (54400B: 16B aligned)
#define OFF_W4  13632      // [o=2][32 padded]
#define OFF_B4  13696
#define OFF_H   13700      // [100][128] per-thread activation columns
#define SMEM_FLOATS (OFF_H + 100 * 128)   // 26500 floats = 106000 bytes

// Packed fp32x2 FMA (Blackwell FFMA2) — 2 FMAs per issue slot.
__device__ __forceinline__ void ffma2(unsigned long long& d,
                                      unsigned long long a,
                                      unsigned long long b) {
    asm("fma.rn.f32x2 %0, %1, %2, %0;" : "+l"(d) : "l"(a), "l"(b));
}
__device__ __forceinline__ unsigned long long pack2(float lo, float hi) {
    unsigned long long r;
    asm("mov.b64 %0, {%1, %2};" : "=l"(r) : "f"(lo), "f"(hi));
    return r;
}
__device__ __forceinline__ void unpack2(unsigned long long v, float& lo, float& hi) {
    asm("mov.b64 {%0, %1}, %2;" : "=f"(lo), "=f"(hi) : "l"(v));
}

__global__ __launch_bounds__(128)
void mlp_kernel(const float* __restrict__ x, const float* __restrict__ nd,
                const float* __restrict__ W1, const float* __restrict__ b1,
                const float* __restrict__ W2, const float* __restrict__ b2,
                const float* __restrict__ W3, const float* __restrict__ b3,
                const float* __restrict__ W4, const float* __restrict__ b4)
{
    extern __shared__ float sm[];
    const int tid = threadIdx.x;

    // ---- stage weights into shared (transpose W2, W3 so output index j is contiguous) ----
    for (int i = tid; i < 10000; i += 128) {
        int j = i / 100, k = i - j * 100;          // W2[j][k]
        sm[OFF_W2T + k * 100 + j] = W2[i];
    }
    for (int i = tid; i < 3200; i += 128) {        // zero-fill padding too
        int k = i >> 5, j = i & 31;                // [k][j], j padded to 32
        sm[OFF_W3T + i] = (j < 30) ? W3[j * 100 + k] : 0.f;
    }
    for (int i = tid; i < 200; i += 128) sm[OFF_W1 + i] = W1[i];
    if (tid < 100) { sm[OFF_B1 + tid] = b1[tid]; sm[OFF_B2 + tid] = b2[tid]; }
    if (tid < 32)  sm[OFF_B3 + tid] = (tid < 30) ? b3[tid] : 0.f;
    if (tid < 64)  sm[OFF_W4 + (tid / 32) * 32 + (tid % 32)] =
                       ((tid % 32) < 30) ? W4[(tid / 32) * 30 + (tid % 32)] : 0.f;
    if (tid < 2)   sm[OFF_B4 + tid] = b4[tid];
    __syncthreads();

    const int p = blockIdx.x * 128 + tid;
    float px = 0.f, py = 0.f;
    if (p < TOTAL) {
        const float2 v = (p < BN) ? ((const float2*)x)[p] : ((const float2*)nd)[p - BN];
        px = v.x; py = v.y;
    }

    float* h = sm + OFF_H;   // this thread owns column `tid` — no cross-thread sharing, no syncs

    // ---- layer 1: 2 -> 100, ReLU ----
    for (int j = 0; j < 100; j++) {
        float v = fmaf(sm[OFF_W1 + 2 * j], px,
                  fmaf(sm[OFF_W1 + 2 * j + 1], py, sm[OFF_B1 + j]));
        h[j * 128 + tid] = fmaxf(v, 0.f);
    }

    // ---- layer 2: 100 -> 100, ReLU. Packed f32x2 accumulators in registers. ----
    unsigned long long acc2[50];
    {
        const unsigned long long* b2p = (const unsigned long long*)(sm + OFF_B2);
        #pragma unroll
        for (int j = 0; j < 50; j++) acc2[j] = b2p[j];
    }
    const ulonglong2* W2t = (const ulonglong2*)(sm + OFF_W2T);
    for (int k = 0; k < 100; k++) {
        const float hk = h[k * 128 + tid];
        const unsigned long long hk2 = pack2(hk, hk);
        const ulonglong2* row = W2t + k * 25;
        #pragma unroll
        for (int j = 0; j < 25; j++) {
            ulonglong2 w = row[j];
            ffma2(acc2[2 * j + 0], w.x, hk2);
            ffma2(acc2[2 * j + 1], w.y, hk2);
        }
    }
    #pragma unroll
    for (int j = 0; j < 50; j++) {
        float lo, hi;
        unpack2(acc2[j], lo, hi);
        h[(2 * j + 0) * 128 + tid] = fmaxf(lo, 0.f);
        h[(2 * j + 1) * 128 + tid] = fmaxf(hi, 0.f);
    }

    // ---- layer 3: 100 -> 30 (padded to 32), packed accumulators ----
    unsigned long long h3p[16];
    {
        const unsigned long long* b3p = (const unsigned long long*)(sm + OFF_B3);
        #pragma unroll
        for (int j = 0; j < 16; j++) h3p[j] = b3p[j];
    }
    const ulonglong2* W3t = (const ulonglong2*)(sm + OFF_W3T);
    for (int k = 0; k < 100; k++) {
        const float hk = h[k * 128 + tid];
        const unsigned long long hk2 = pack2(hk, hk);
        const ulonglong2* row = W3t + k * 8;
        #pragma unroll
        for (int j = 0; j < 8; j++) {
            ulonglong2 w = row[j];
            ffma2(h3p[2 * j + 0], w.x, hk2);
            ffma2(h3p[2 * j + 1], w.y, hk2);
        }
    }

    // ---- layer 4: 30 -> 2, linear (padded lanes have zero weights) ----
    float o0 = sm[OFF_B4 + 0], o1 = sm[OFF_B4 + 1];
    #pragma unroll
    for (int j = 0; j < 15; j++) {          // 15 pairs = 30 real outputs
        float lo, hi;
        unpack2(h3p[j], lo, hi);
        lo = fmaxf(lo, 0.f); hi = fmaxf(hi, 0.f);
        o0 = fmaf(sm[OFF_W4 + 2 * j], lo, fmaf(sm[OFF_W4 + 2 * j + 1], hi, o0));
        o1 = fmaf(sm[OFF_W4 + 32 + 2 * j], lo, fmaf(sm[OFF_W4 + 32 + 2 * j + 1], hi, o1));
    }

    if (p < TOTAL) ((float2*)g_feat)[p] = make_float2(o0, o1);
}

// ---------------- routing kernel: one block per query b ----------------
// warp d in [0,8) handles path step d, lane k in [0,32) handles neighbor k.
__global__ __launch_bounds__(256)
void route_kernel(const int* __restrict__ nbr_idx, const int* __restrict__ labels,
                  float* __restrict__ out)
{
    __shared__ float p_s[CC];
    __shared__ float terms[DD - 1];

    const int b = blockIdx.x;
    const int tid = threadIdx.x;
    const int d = tid >> 5, lane = tid & 31;

    if (tid < CC) p_s[tid] = 0.f;
    __syncthreads();

    const float2 q = ((const float2*)g_feat)[b];
    const int idx = nbr_idx[b * (DD * KK) + tid];    // coalesced: [B][D][K]
    const float2 g = ((const float2*)g_feat)[BN + idx];

    const float dx = g.x - q.x + 1e-6f;              // F.pairwise_distance eps on the diff
    const float dy = g.y - q.y + 1e-6f;
    const float neg = -sqrtf(fmaf(dx, dx, dy * dy));

    float m = neg;
    #pragma unroll
    for (int o = 16; o > 0; o >>= 1) m = fmaxf(m, __shfl_xor_sync(0xffffffffu, m, o));
    const float e = expf(neg - m);
    float s = e;
    #pragma unroll
    for (int o = 16; o > 0; o >>= 1) s += __shfl_xor_sync(0xffffffffu, s, o);

    if (d < DD - 1) {
        // max_k softmax == exp(0)/s == 1/s exactly (argmax lane has neg-m == 0.0f)
        if (lane == 0) terms[d] = logf(1.0f / s + 1e-4f);
    } else {
        // final step: p[c] += sm_k for each neighbor's label c  (einsum vs one-hot)
        const int c = labels[idx];
        atomicAdd(&p_s[c], e / s);
    }
    __syncthreads();

    if (tid < CC) {
        float t = terms[0] + terms[1] + terms[2] + terms[3] + terms[4] + terms[5] + terms[6];
        out[(long)b * CC + tid] = logf(p_s[tid] + 1e-4f) + t;
    }
}

extern "C" void kernel_launch(void* const* d_in, const int* in_sizes, int n_in,
                              void* d_out, int out_size)
{
    const float* x      = (const float*)d_in[0];
    const float* nd     = (const float*)d_in[1];
    const float* W1     = (const float*)d_in[2];
    const float* b1     = (const float*)d_in[3];
    const float* W2     = (const float*)d_in[4];
    const float* b2     = (const float*)d_in[5];
    const float* W3     = (const float*)d_in[6];
    const float* b3     = (const float*)d_in[7];
    const float* W4     = (const float*)d_in[8];
    const float* b4     = (const float*)d_in[9];
    const int*   labels = (const int*)d_in[10];
    const int*   nbr    = (const int*)d_in[11];
    float* out = (float*)d_out;

    cudaFuncSetAttribute(mlp_kernel, cudaFuncAttributeMaxDynamicSharedMemorySize,
                         SMEM_FLOATS * (int)sizeof(float));

    const int blocks = (TOTAL + 127) / 128;
    mlp_kernel<<<blocks, 128, SMEM_FLOATS * sizeof(float)>>>(
        x, nd, W1, b1, W2, b2, W3, b3, W4, b4);
    route_kernel<<<BN, 256>>>(nbr, labels, out);
}

// round 4
// speedup vs baseline: 1.3815x; 1.3019x over previous
#include <cuda_runtime.h>
#include <math.h>

#define BN 8192
#define NN 100000
#define DD 8
#define KK 32
#define CC 100
#define TOTAL (BN + NN)

#define NSTR 136          // smem column stride (floats): bank = 8t+g -> conflict-free B frags
#define KT   13           // k-tiles of 8 covering K=100 (pad 104)
#define MT2  7            // m-tiles of 16 covering M=100 (pad 112)
#define MT3  2            // m-tiles of 16 covering M=30  (pad 32)
#define W2P_SZ (KT * MT2 * 128)   // 11648 elements
#define W3P_SZ (KT * MT3 * 128)   // 3328 elements

// Feature scratch: [0..BN) queries, [BN..TOTAL) nodes, as (x,y) float pairs.
__device__ float g_feat[TOTAL * 2];

// Weights pre-split (3xTF32) and pre-packed in mma A-fragment order:
// id = ((kt*MT+mt)*32 + lane)*4 + r ; row = mt*16 + g + (r&1)*8 ; col = kt*8 + t + (r>>1)*4
__device__ uint4 g_W2hi[W2P_SZ / 4], g_W2lo[W2P_SZ / 4];
__device__ uint4 g_W3hi[W3P_SZ / 4], g_W3lo[W3P_SZ / 4];

__device__ __forceinline__ unsigned f2tf(float x) {
    unsigned r;
    asm("cvt.rna.tf32.f32 %0, %1;" : "=r"(r) : "f"(x));
    return r;
}

__device__ __forceinline__ void mma8(float (&c)[4], const uint4& a, unsigned b0, unsigned b1) {
    asm("mma.sync.aligned.m16n8k8.row.col.f32.tf32.tf32.f32 "
        "{%0,%1,%2,%3}, {%4,%5,%6,%7}, {%8,%9}, {%0,%1,%2,%3};"
        : "+f"(c[0]), "+f"(c[1]), "+f"(c[2]), "+f"(c[3])
        : "r"(a.x), "r"(a.y), "r"(a.z), "r"(a.w), "r"(b0), "r"(b1));
}

// ---------------- pack kernel: split W2/W3 into hi/lo tf32 fragments ----------------
__global__ void pack_kernel(const float* __restrict__ W2, const float* __restrict__ W3)
{
    const int stride = gridDim.x * blockDim.x;
    for (int idx = blockIdx.x * blockDim.x + threadIdx.x;
         idx < W2P_SZ + W3P_SZ; idx += stride) {
        const bool is3 = idx >= W2P_SZ;
        const int id = is3 ? idx - W2P_SZ : idx;
        const int r = id & 3, lane = (id >> 2) & 31, q = id >> 7;
        const int nmt = is3 ? MT3 : MT2;
        const int mt = q % nmt, kt = q / nmt;
        const int g = lane >> 2, t = lane & 3;
        const int row = mt * 16 + g + (r & 1) * 8;
        const int col = kt * 8 + t + (r >> 1) * 4;
        float w = 0.f;
        if (is3) { if (row < 30 && col < 100) w = W3[row * 100 + col]; }
        else     { if (row < 100 && col < 100) w = W2[row * 100 + col]; }
        const unsigned hi = f2tf(w);
        const unsigned lo = f2tf(w - __uint_as_float(hi));
        if (is3) { ((unsigned*)g_W3hi)[id] = hi; ((unsigned*)g_W3lo)[id] = lo; }
        else     { ((unsigned*)g_W2hi)[id] = hi; ((unsigned*)g_W2lo)[id] = lo; }
    }
}

// ---------------- MLP kernel: 256 threads, 128 points per block ----------------
// smem Hs[104][NSTR] holds h1, then h2, then h3 (reused between syncs).
__global__ __launch_bounds__(256)
void mlp_kernel(const float* __restrict__ x, const float* __restrict__ nd,
                const float* __restrict__ W1, const float* __restrict__ b1,
                const float* __restrict__ b2, const float* __restrict__ b3,
                const float* __restrict__ W4, const float* __restrict__ b4)
{
    extern __shared__ float Hs[];
    const int tid = threadIdx.x;
    const int lane = tid & 31, warp = tid >> 5;
    const int g = lane >> 2, t = lane & 3;
    const int pbase = blockIdx.x * 128;
    const int n0 = warp * 16;              // each warp owns 16 points (2 n-tiles of 8)

    // ---- layer 1: 2 -> 100, ReLU. Two threads per point (j-halves). ----
    {
        const int p = tid & 127, half = tid >> 7;
        const int pg = pbase + p;
        float px = 0.f, py = 0.f;
        if (pg < TOTAL) {
            const float2 v = (pg < BN) ? ((const float2*)x)[pg] : ((const float2*)nd)[pg - BN];
            px = v.x; py = v.y;
        }
        const int j0 = half * 50;
        for (int j = j0; j < j0 + 50; j++) {
            float v = fmaf(W1[2 * j], px, fmaf(W1[2 * j + 1], py, b1[j]));
            Hs[j * NSTR + p] = fmaxf(v, 0.f);
        }
        for (int i = tid; i < 4 * NSTR; i += 256) Hs[100 * NSTR + i] = 0.f;  // zero pad rows 100..103
    }
    __syncthreads();

    // ---- layer 2: 100 -> 100 via 3xTF32 mma ----
    float C[MT2][2][4];
    #pragma unroll
    for (int mt = 0; mt < MT2; mt++)
        #pragma unroll
        for (int nt = 0; nt < 2; nt++)
            #pragma unroll
            for (int r = 0; r < 4; r++) C[mt][nt][r] = 0.f;

    for (int kt = 0; kt < KT; kt++) {
        uint4 ah[MT2], al[MT2];
        #pragma unroll
        for (int mt = 0; mt < MT2; mt++) {
            const int base = (kt * MT2 + mt) * 32 + lane;
            ah[mt] = g_W2hi[base];
            al[mt] = g_W2lo[base];
        }
        // B fragments for 2 n-tiles, split on the fly
        const float r0a = Hs[(kt * 8 + t) * NSTR + n0 + g];
        const float r1a = Hs[(kt * 8 + t + 4) * NSTR + n0 + g];
        const float r0b = Hs[(kt * 8 + t) * NSTR + n0 + 8 + g];
        const float r1b = Hs[(kt * 8 + t + 4) * NSTR + n0 + 8 + g];
        const unsigned b0ha = f2tf(r0a), b1ha = f2tf(r1a);
        const unsigned b0la = f2tf(r0a - __uint_as_float(b0ha));
        const unsigned b1la = f2tf(r1a - __uint_as_float(b1ha));
        const unsigned b0hb = f2tf(r0b), b1hb = f2tf(r1b);
        const unsigned b0lb = f2tf(r0b - __uint_as_float(b0hb));
        const unsigned b1lb = f2tf(r1b - __uint_as_float(b1hb));
        #pragma unroll
        for (int mt = 0; mt < MT2; mt++) {
            mma8(C[mt][0], ah[mt], b0ha, b1ha);
            mma8(C[mt][0], ah[mt], b0la, b1la);
            mma8(C[mt][0], al[mt], b0ha, b1ha);
            mma8(C[mt][1], ah[mt], b0hb, b1hb);
            mma8(C[mt][1], ah[mt], b0lb, b1lb);
            mma8(C[mt][1], al[mt], b0hb, b1hb);
        }
    }
    __syncthreads();   // all layer-2 reads of Hs complete

    // write h2 = relu(C + b2) back into Hs (rows 0..99 real, 100..103 zero)
    #pragma unroll
    for (int mt = 0; mt < MT2; mt++)
        #pragma unroll
        for (int half = 0; half < 2; half++) {
            const int row = mt * 16 + g + half * 8;
            if (row < 104) {
                const float bias = (row < 100) ? b2[row] : 0.f;
                #pragma unroll
                for (int nt = 0; nt < 2; nt++) {
                    float v0 = C[mt][nt][2 * half + 0] + bias;
                    float v1 = C[mt][nt][2 * half + 1] + bias;
                    if (row >= 100) { v0 = 0.f; v1 = 0.f; }
                    else { v0 = fmaxf(v0, 0.f); v1 = fmaxf(v1, 0.f); }
                    Hs[row * NSTR + n0 + nt * 8 + 2 * t] = v0;
                    Hs[row * NSTR + n0 + nt * 8 + 2 * t + 1] = v1;
                }
            }
        }
    __syncthreads();

    // ---- layer 3: 100 -> 30 via 3xTF32 mma ----
    float D[MT3][2][4];
    #pragma unroll
    for (int mt = 0; mt < MT3; mt++)
        #pragma unroll
        for (int nt = 0; nt < 2; nt++)
            #pragma unroll
            for (int r = 0; r < 4; r++) D[mt][nt][r] = 0.f;

    for (int kt = 0; kt < KT; kt++) {
        uint4 ah[MT3], al[MT3];
        #pragma unroll
        for (int mt = 0; mt < MT3; mt++) {
            const int base = (kt * MT3 + mt) * 32 + lane;
            ah[mt] = g_W3hi[base];
            al[mt] = g_W3lo[base];
        }
        const float r0a = Hs[(kt * 8 + t) * NSTR + n0 + g];
        const float r1a = Hs[(kt * 8 + t + 4) * NSTR + n0 + g];
        const float r0b = Hs[(kt * 8 + t) * NSTR + n0 + 8 + g];
        const float r1b = Hs[(kt * 8 + t + 4) * NSTR + n0 + 8 + g];
        const unsigned b0ha = f2tf(r0a), b1ha = f2tf(r1a);
        const unsigned b0la = f2tf(r0a - __uint_as_float(b0ha));
        const unsigned b1la = f2tf(r1a - __uint_as_float(b1ha));
        const unsigned b0hb = f2tf(r0b), b1hb = f2tf(r1b);
        const unsigned b0lb = f2tf(r0b - __uint_as_float(b0hb));
        const unsigned b1lb = f2tf(r1b - __uint_as_float(b1hb));
        #pragma unroll
        for (int mt = 0; mt < MT3; mt++) {
            mma8(D[mt][0], ah[mt], b0ha, b1ha);
            mma8(D[mt][0], ah[mt], b0la, b1la);
            mma8(D[mt][0], al[mt], b0ha, b1ha);
            mma8(D[mt][1], ah[mt], b0hb, b1hb);
            mma8(D[mt][1], ah[mt], b0lb, b1lb);
            mma8(D[mt][1], al[mt], b0hb, b1hb);
        }
    }
    __syncthreads();

    // write h3 = relu(D + b3) into Hs rows 0..31 (rows 30,31 zeroed)
    #pragma unroll
    for (int mt = 0; mt < MT3; mt++)
        #pragma unroll
        for (int half = 0; half < 2; half++) {
            const int row = mt * 16 + g + half * 8;
            const float bias = (row < 30) ? b3[row] : 0.f;
            #pragma unroll
            for (int nt = 0; nt < 2; nt++) {
                float v0 = D[mt][nt][2 * half + 0] + bias;
                float v1 = D[mt][nt][2 * half + 1] + bias;
                v0 = (row < 30) ? fmaxf(v0, 0.f) : 0.f;
                v1 = (row < 30) ? fmaxf(v1, 0.f) : 0.f;
                Hs[row * NSTR + n0 + nt * 8 + 2 * t] = v0;
                Hs[row * NSTR + n0 + nt * 8 + 2 * t + 1] = v1;
            }
        }
    __syncthreads();

    // ---- layer 4: 30 -> 2, one thread per point ----
    if (tid < 128) {
        const int pg = pbase + tid;
        float o0 = b4[0], o1 = b4[1];
        #pragma unroll
        for (int j = 0; j < 30; j++) {
            const float h = Hs[j * NSTR + tid];
            o0 = fmaf(W4[j], h, o0);
            o1 = fmaf(W4[30 + j], h, o1);
        }
        if (pg < TOTAL) ((float2*)g_feat)[pg] = make_float2(o0, o1);
    }
}

// ---------------- routing kernel: one block per query b ----------------
__global__ __launch_bounds__(256)
void route_kernel(const int* __restrict__ nbr_idx, const int* __restrict__ labels,
                  float* __restrict__ out)
{
    __shared__ float p_s[CC];
    __shared__ float terms[DD - 1];

    const int b = blockIdx.x;
    const int tid = threadIdx.x;
    const int d = tid >> 5, lane = tid & 31;

    if (tid < CC) p_s[tid] = 0.f;
    __syncthreads();

    const float2 q = ((const float2*)g_feat)[b];
    const int idx = nbr_idx[b * (DD * KK) + tid];    // coalesced: [B][D][K]
    const float2 g = ((const float2*)g_feat)[BN + idx];

    const float dx = g.x - q.x + 1e-6f;              // pairwise_distance eps on the diff
    const float dy = g.y - q.y + 1e-6f;
    const float neg = -sqrtf(fmaf(dx, dx, dy * dy));

    float m = neg;
    #pragma unroll
    for (int o = 16; o > 0; o >>= 1) m = fmaxf(m, __shfl_xor_sync(0xffffffffu, m, o));
    const float e = __expf(neg - m);
    float s = e;
    #pragma unroll
    for (int o = 16; o > 0; o >>= 1) s += __shfl_xor_sync(0xffffffffu, s, o);

    if (d < DD - 1) {
        // max_k softmax == 1/s exactly (argmax lane exp(0)=1)
        if (lane == 0) terms[d] = logf(1.0f / s + 1e-4f);
    } else {
        const int c = labels[idx];
        atomicAdd(&p_s[c], e / s);
    }
    __syncthreads();

    if (tid < CC) {
        float tsum = terms[0] + terms[1] + terms[2] + terms[3] + terms[4] + terms[5] + terms[6];
        out[(long)b * CC + tid] = logf(p_s[tid] + 1e-4f) + tsum;
    }
}

extern "C" void kernel_launch(void* const* d_in, const int* in_sizes, int n_in,
                              void* d_out, int out_size)
{
    const float* x      = (const float*)d_in[0];
    const float* nd     = (const float*)d_in[1];
    const float* W1     = (const float*)d_in[2];
    const float* b1     = (const float*)d_in[3];
    const float* W2     = (const float*)d_in[4];
    const float* b2     = (const float*)d_in[5];
    const float* W3     = (const float*)d_in[6];
    const float* b3     = (const float*)d_in[7];
    const float* W4     = (const float*)d_in[8];
    const float* b4     = (const float*)d_in[9];
    const int*   labels = (const int*)d_in[10];
    const int*   nbr    = (const int*)d_in[11];
    float* out = (float*)d_out;

    const int smem = 104 * NSTR * (int)sizeof(float);   // 56576 bytes
    cudaFuncSetAttribute(mlp_kernel, cudaFuncAttributeMaxDynamicSharedMemorySize, smem);

    pack_kernel<<<60, 256>>>(W2, W3);
    const int blocks = (TOTAL + 127) / 128;
    mlp_kernel<<<blocks, 256, smem>>>(x, nd, W1, b1, b2, b3, W4, b4);
    route_kernel<<<BN, 256>>>(nbr, labels, out);
}

// round 5
// speedup vs baseline: 1.9566x; 1.4163x over previous
#include <cuda_runtime.h>
#include <cuda_bf16.h>
#include <math.h>

#define BN 8192
#define NN 100000
#define DD 8
#define KK 32
#define CC 100
#define TOTAL (BN + NN)

#define NSTR 132          // stride mod 32 == 4 -> B-frag LDS conflict-free (bank 8t+g)
#define KT   7            // k-tiles of 16 covering K=100 (pad 112)
#define MT2  7            // m-tiles of 16 covering M=100 (pad 112)
#define MT3  2            // m-tiles of 16 covering M=30  (pad 32)
#define NW2  (KT * MT2 * 128)   // 6272 u32 regs (each = 2 bf16)
#define NW3  (KT * MT3 * 128)   // 1792

// Feature scratch: [0..BN) queries, [BN..TOTAL) nodes, as (x,y) float pairs.
__device__ float g_feat[TOTAL * 2];

// Weights split 2-way into bf16 (hi + residual lo), packed in m16n8k16 A-fragment order.
// u32 id = ((kt*MT+mt)*32 + lane)*4 + r ; row = mt*16+g+(r&1)*8 ; cols = kt*16+2t+(r>>1)*8 +{0,1}
__device__ unsigned g_W2hi[NW2], g_W2lo[NW2];
__device__ unsigned g_W3hi[NW3], g_W3lo[NW3];

__device__ __forceinline__ unsigned bf2(float lo, float hi) {  // pack {lo, hi} as bf16x2
    unsigned r;
    asm("cvt.rn.bf16x2.f32 %0, %1, %2;" : "=r"(r) : "f"(hi), "f"(lo));
    return r;
}
__device__ __forceinline__ float blo(unsigned p) { return __uint_as_float(p << 16); }
__device__ __forceinline__ float bhi(unsigned p) { return __uint_as_float(p & 0xffff0000u); }

__device__ __forceinline__ void mma16(float (&c)[4], const uint4& a, unsigned b0, unsigned b1) {
    asm("mma.sync.aligned.m16n8k16.row.col.f32.bf16.bf16.f32 "
        "{%0,%1,%2,%3}, {%4,%5,%6,%7}, {%8,%9}, {%0,%1,%2,%3};"
        : "+f"(c[0]), "+f"(c[1]), "+f"(c[2]), "+f"(c[3])
        : "r"(a.x), "r"(a.y), "r"(a.z), "r"(a.w), "r"(b0), "r"(b1));
}

// ---------------- pack kernel: split W2/W3 into bf16 hi/lo fragment arrays ----------------
__global__ void pack_kernel(const float* __restrict__ W2, const float* __restrict__ W3)
{
    const int stride = gridDim.x * blockDim.x;
    for (int idx = blockIdx.x * blockDim.x + threadIdx.x; idx < NW2 + NW3; idx += stride) {
        const bool is3 = idx >= NW2;
        const int id = is3 ? idx - NW2 : idx;
        const int r = id & 3, lane = (id >> 2) & 31, q = id >> 7;
        const int nmt = is3 ? MT3 : MT2;
        const int mt = q % nmt, kt = q / nmt;
        const int g = lane >> 2, t = lane & 3;
        const int row = mt * 16 + g + (r & 1) * 8;
        const int col = kt * 16 + 2 * t + (r >> 1) * 8;
        const int rmax = is3 ? 30 : 100;
        const float* W = is3 ? W3 : W2;
        float w0 = 0.f, w1 = 0.f;
        if (row < rmax) {
            if (col < 100)     w0 = W[row * 100 + col];
            if (col + 1 < 100) w1 = W[row * 100 + col + 1];
        }
        const float h0 = __bfloat162float(__float2bfloat16_rn(w0));
        const float h1 = __bfloat162float(__float2bfloat16_rn(w1));
        const unsigned hp = bf2(h0, h1);          // exact: h0,h1 already bf16 values
        const unsigned lp = bf2(w0 - h0, w1 - h1);
        if (is3) { g_W3hi[id] = hp; g_W3lo[id] = lp; }
        else     { g_W2hi[id] = hp; g_W2lo[id] = lp; }
    }
}

// ---------------- MLP kernel: 256 threads, 128 points per block ----------------
// smem Hs[112][NSTR] holds h1 (rows 0..99 + zero pad), then h2, then h3.
__global__ __launch_bounds__(256)
void mlp_kernel(const float* __restrict__ x, const float* __restrict__ nd,
                const float* __restrict__ W1, const float* __restrict__ b1,
                const float* __restrict__ b2, const float* __restrict__ b3,
                const float* __restrict__ W4, const float* __restrict__ b4)
{
    extern __shared__ float Hs[];
    const int tid = threadIdx.x;
    const int lane = tid & 31, warp = tid >> 5;
    const int g = lane >> 2, t = lane & 3;
    const int pbase = blockIdx.x * 128;
    const int n0 = warp * 16;              // each warp owns 16 points (2 n-tiles of 8)

    // ---- layer 1: 2 -> 100, ReLU. Two threads per point (j-halves). ----
    {
        const int p = tid & 127, half = tid >> 7;
        const int pg = pbase + p;
        float px = 0.f, py = 0.f;
        if (pg < TOTAL) {
            const float2 v = (pg < BN) ? ((const float2*)x)[pg] : ((const float2*)nd)[pg - BN];
            px = v.x; py = v.y;
        }
        const int j0 = half * 50;
        for (int j = j0; j < j0 + 50; j++) {
            float v = fmaf(W1[2 * j], px, fmaf(W1[2 * j + 1], py, b1[j]));
            Hs[j * NSTR + p] = fmaxf(v, 0.f);
        }
        for (int i = tid; i < 12 * NSTR; i += 256) Hs[100 * NSTR + i] = 0.f;  // zero rows 100..111
    }
    __syncthreads();

    const uint4* W2h4 = (const uint4*)g_W2hi;
    const uint4* W2l4 = (const uint4*)g_W2lo;
    const uint4* W3h4 = (const uint4*)g_W3hi;
    const uint4* W3l4 = (const uint4*)g_W3lo;

    // ---- layer 2: 100 -> 100 via bf16 split-2 mma (3 products) ----
    float C[MT2][2][4];
    #pragma unroll
    for (int mt = 0; mt < MT2; mt++)
        #pragma unroll
        for (int nt = 0; nt < 2; nt++)
            #pragma unroll
            for (int r = 0; r < 4; r++) C[mt][nt][r] = 0.f;

    for (int kt = 0; kt < KT; kt++) {
        uint4 ah[MT2], al[MT2];
        #pragma unroll
        for (int mt = 0; mt < MT2; mt++) {
            const int base = (kt * MT2 + mt) * 32 + lane;
            ah[mt] = W2h4[base];
            al[mt] = W2l4[base];
        }
        const int k0 = kt * 16 + 2 * t;
        unsigned bh[2][2], bl[2][2];
        #pragma unroll
        for (int nt = 0; nt < 2; nt++) {
            const int c = n0 + nt * 8 + g;
            const float r0 = Hs[(k0 + 0) * NSTR + c];
            const float r1 = Hs[(k0 + 1) * NSTR + c];
            const float r2 = Hs[(k0 + 8) * NSTR + c];
            const float r3 = Hs[(k0 + 9) * NSTR + c];
            bh[nt][0] = bf2(r0, r1);
            bh[nt][1] = bf2(r2, r3);
            bl[nt][0] = bf2(r0 - blo(bh[nt][0]), r1 - bhi(bh[nt][0]));
            bl[nt][1] = bf2(r2 - blo(bh[nt][1]), r3 - bhi(bh[nt][1]));
        }
        #pragma unroll
        for (int mt = 0; mt < MT2; mt++)
            #pragma unroll
            for (int nt = 0; nt < 2; nt++) {
                mma16(C[mt][nt], ah[mt], bh[nt][0], bh[nt][1]);
                mma16(C[mt][nt], ah[mt], bl[nt][0], bl[nt][1]);
                mma16(C[mt][nt], al[mt], bh[nt][0], bh[nt][1]);
            }
    }
    __syncthreads();   // all layer-2 reads of Hs complete

    // write h2 = relu(C + b2) into Hs rows 0..111 (rows >=100 zeroed)
    #pragma unroll
    for (int mt = 0; mt < MT2; mt++)
        #pragma unroll
        for (int half = 0; half < 2; half++) {
            const int row = mt * 16 + g + half * 8;
            const float bias = (row < 100) ? b2[row] : 0.f;
            #pragma unroll
            for (int nt = 0; nt < 2; nt++) {
                float v0 = C[mt][nt][2 * half + 0] + bias;
                float v1 = C[mt][nt][2 * half + 1] + bias;
                if (row >= 100) { v0 = 0.f; v1 = 0.f; }
                else { v0 = fmaxf(v0, 0.f); v1 = fmaxf(v1, 0.f); }
                Hs[row * NSTR + n0 + nt * 8 + 2 * t] = v0;
                Hs[row * NSTR + n0 + nt * 8 + 2 * t + 1] = v1;
            }
        }
    __syncthreads();

    // ---- layer 3: 100 -> 30 via bf16 split-2 mma ----
    float D[MT3][2][4];
    #pragma unroll
    for (int mt = 0; mt < MT3; mt++)
        #pragma unroll
        for (int nt = 0; nt < 2; nt++)
            #pragma unroll
            for (int r = 0; r < 4; r++) D[mt][nt][r] = 0.f;

    for (int kt = 0; kt < KT; kt++) {
        uint4 ah[MT3], al[MT3];
        #pragma unroll
        for (int mt = 0; mt < MT3; mt++) {
            const int base = (kt * MT3 + mt) * 32 + lane;
            ah[mt] = W3h4[base];
            al[mt] = W3l4[base];
        }
        const int k0 = kt * 16 + 2 * t;
        unsigned bh[2][2], bl[2][2];
        #pragma unroll
        for (int nt = 0; nt < 2; nt++) {
            const int c = n0 + nt * 8 + g;
            const float r0 = Hs[(k0 + 0) * NSTR + c];
            const float r1 = Hs[(k0 + 1) * NSTR + c];
            const float r2 = Hs[(k0 + 8) * NSTR + c];
            const float r3 = Hs[(k0 + 9) * NSTR + c];
            bh[nt][0] = bf2(r0, r1);
            bh[nt][1] = bf2(r2, r3);
            bl[nt][0] = bf2(r0 - blo(bh[nt][0]), r1 - bhi(bh[nt][0]));
            bl[nt][1] = bf2(r2 - blo(bh[nt][1]), r3 - bhi(bh[nt][1]));
        }
        #pragma unroll
        for (int mt = 0; mt < MT3; mt++)
            #pragma unroll
            for (int nt = 0; nt < 2; nt++) {
                mma16(D[mt][nt], ah[mt], bh[nt][0], bh[nt][1]);
                mma16(D[mt][nt], ah[mt], bl[nt][0], bl[nt][1]);
                mma16(D[mt][nt], al[mt], bh[nt][0], bh[nt][1]);
            }
    }
    __syncthreads();

    // write h3 = relu(D + b3) into Hs rows 0..31 (rows 30,31 zeroed)
    #pragma unroll
    for (int mt = 0; mt < MT3; mt++)
        #pragma unroll
        for (int half = 0; half < 2; half++) {
            const int row = mt * 16 + g + half * 8;
            const float bias = (row < 30) ? b3[row] : 0.f;
            #pragma unroll
            for (int nt = 0; nt < 2; nt++) {
                float v0 = D[mt][nt][2 * half + 0] + bias;
                float v1 = D[mt][nt][2 * half + 1] + bias;
                v0 = (row < 30) ? fmaxf(v0, 0.f) : 0.f;
                v1 = (row < 30) ? fmaxf(v1, 0.f) : 0.f;
                Hs[row * NSTR + n0 + nt * 8 + 2 * t] = v0;
                Hs[row * NSTR + n0 + nt * 8 + 2 * t + 1] = v1;
            }
        }
    __syncthreads();

    // ---- layer 4: 30 -> 2, one thread per point ----
    if (tid < 128) {
        const int pg = pbase + tid;
        float o0 = b4[0], o1 = b4[1];
        #pragma unroll
        for (int j = 0; j < 30; j++) {
            const float h = Hs[j * NSTR + tid];
            o0 = fmaf(W4[j], h, o0);
            o1 = fmaf(W4[30 + j], h, o1);
        }
        if (pg < TOTAL) ((float2*)g_feat)[pg] = make_float2(o0, o1);
    }
}

// ---------------- routing kernel: one block per query b ----------------
__global__ __launch_bounds__(256)
void route_kernel(const int* __restrict__ nbr_idx, const int* __restrict__ labels,
                  float* __restrict__ out)
{
    __shared__ float p_s[CC];
    __shared__ float terms[DD - 1];

    const int b = blockIdx.x;
    const int tid = threadIdx.x;
    const int d = tid >> 5, lane = tid & 31;

    if (tid < CC) p_s[tid] = 0.f;
    __syncthreads();

    const float2 q = ((const float2*)g_feat)[b];
    const int idx = nbr_idx[b * (DD * KK) + tid];    // coalesced: [B][D][K]
    const float2 g = ((const float2*)g_feat)[BN + idx];

    const float dx = g.x - q.x + 1e-6f;              // pairwise_distance eps on the diff
    const float dy = g.y - q.y + 1e-6f;
    const float neg = -sqrtf(fmaf(dx, dx, dy * dy));

    float m = neg;
    #pragma unroll
    for (int o = 16; o > 0; o >>= 1) m = fmaxf(m, __shfl_xor_sync(0xffffffffu, m, o));
    const float e = __expf(neg - m);
    float s = e;
    #pragma unroll
    for (int o = 16; o > 0; o >>= 1) s += __shfl_xor_sync(0xffffffffu, s, o);

    if (d < DD - 1) {
        // max_k softmax == 1/s exactly (argmax lane exp(0)=1)
        if (lane == 0) terms[d] = __logf(1.0f / s + 1e-4f);
    } else {
        const int c = labels[idx];
        atomicAdd(&p_s[c], e / s);
    }
    __syncthreads();

    if (tid < CC) {
        float tsum = terms[0] + terms[1] + terms[2] + terms[3] + terms[4] + terms[5] + terms[6];
        out[(long)b * CC + tid] = __logf(p_s[tid] + 1e-4f) + tsum;
    }
}

extern "C" void kernel_launch(void* const* d_in, const int* in_sizes, int n_in,
                              void* d_out, int out_size)
{
    const float* x      = (const float*)d_in[0];
    const float* nd     = (const float*)d_in[1];
    const float* W1     = (const float*)d_in[2];
    const float* b1     = (const float*)d_in[3];
    const float* W2     = (const float*)d_in[4];
    const float* b2     = (const float*)d_in[5];
    const float* W3     = (const float*)d_in[6];
    const float* b3     = (const float*)d_in[7];
    const float* W4     = (const float*)d_in[8];
    const float* b4     = (const float*)d_in[9];
    const int*   labels = (const int*)d_in[10];
    const int*   nbr    = (const int*)d_in[11];
    float* out = (float*)d_out;

    const int smem = 112 * NSTR * (int)sizeof(float);   // 59136 bytes
    cudaFuncSetAttribute(mlp_kernel, cudaFuncAttributeMaxDynamicSharedMemorySize, smem);

    pack_kernel<<<32, 256>>>(W2, W3);
    const int blocks = (TOTAL + 127) / 128;
    mlp_kernel<<<blocks, 256, smem>>>(x, nd, W1, b1, b2, b3, W4, b4);
    route_kernel<<<BN, 256>>>(nbr, labels, out);
}

// round 7
// speedup vs baseline: 2.4805x; 1.2677x over previous
#include <cuda_runtime.h>
#include <cuda_bf16.h>
#include <math.h>

#define BN 8192
#define NN 100000
#define DD 8
#define KK 32
#define CC 100
#define TOTAL (BN + NN)
#define NTILES ((TOTAL + 127) / 128)   // 846
#define GRID_MLP 296                   // 2 blocks/SM persistent

#define NSTR 132          // stride mod 32 == 4 -> B-frag LDS conflict-free
#define KT   7            // k-tiles of 16 covering K=100 (pad 112)
#define MT2  7            // m-tiles of 16 covering M=100 (pad 112)
#define MT3  2            // m-tiles of 16 covering M=30  (pad 32)
#define NW2  (KT * MT2 * 128)   // 6272 u32
#define NW3  (KT * MT3 * 128)   // 1792 u32

// ---- smem layout (bytes) ----
#define SM_HS    0                       // Hs fp32 [112][NSTR] = 59136
#define SM_W2FH  59136                   // W2 hi frags: 6272 u32 = 25088
#define SM_W2FL  84224                   // W2 lo frags: 25088
#define SM_MISC  109312                  // mf floats [494]
#define SMEM_TOTAL 111360

// Feature scratch: [0..BN) queries, [BN..TOTAL) nodes, (x,y) pairs.
__device__ float g_feat[TOTAL * 2];

// Weights split 2-way into bf16 (hi + residual lo), packed in m16n8k16 A-fragment order.
__device__ unsigned g_W2hi[NW2], g_W2lo[NW2];
__device__ unsigned g_W3hi[NW3], g_W3lo[NW3];

__device__ __forceinline__ unsigned bf2(float lo, float hi) {  // pack {lo, hi} bf16x2
    unsigned r;
    asm("cvt.rn.bf16x2.f32 %0, %1, %2;" : "=r"(r) : "f"(hi), "f"(lo));
    return r;
}
__device__ __forceinline__ float blo(unsigned p) { return __uint_as_float(p << 16); }
__device__ __forceinline__ float bhi(unsigned p) { return __uint_as_float(p & 0xffff0000u); }

__device__ __forceinline__ void mma16(float (&c)[4], const uint4& a, unsigned b0, unsigned b1) {
    asm("mma.sync.aligned.m16n8k16.row.col.f32.bf16.bf16.f32 "
        "{%0,%1,%2,%3}, {%4,%5,%6,%7}, {%8,%9}, {%0,%1,%2,%3};"
        : "+f"(c[0]), "+f"(c[1]), "+f"(c[2]), "+f"(c[3])
        : "r"(a.x), "r"(a.y), "r"(a.z), "r"(a.w), "r"(b0), "r"(b1));
}

// ---------------- pack kernel: split W2/W3 into bf16 hi/lo fragment arrays ----------------
__global__ void pack_kernel(const float* __restrict__ W2, const float* __restrict__ W3)
{
    const int stride = gridDim.x * blockDim.x;
    for (int idx = blockIdx.x * blockDim.x + threadIdx.x; idx < NW2 + NW3; idx += stride) {
        const bool is3 = idx >= NW2;
        const int id = is3 ? idx - NW2 : idx;
        const int r = id & 3, lane = (id >> 2) & 31, q = id >> 7;
        const int nmt = is3 ? MT3 : MT2;
        const int mt = q % nmt, kt = q / nmt;
        const int g = lane >> 2, t = lane & 3;
        const int row = mt * 16 + g + (r & 1) * 8;
        const int col = kt * 16 + 2 * t + (r >> 1) * 8;
        const int rmax = is3 ? 30 : 100;
        const float* W = is3 ? W3 : W2;
        float w0 = 0.f, w1 = 0.f;
        if (row < rmax) {
            if (col < 100)     w0 = W[row * 100 + col];
            if (col + 1 < 100) w1 = W[row * 100 + col + 1];
        }
        const float h0 = __bfloat162float(__float2bfloat16_rn(w0));
        const float h1 = __bfloat162float(__float2bfloat16_rn(w1));
        const unsigned hp = bf2(h0, h1);
        const unsigned lp = bf2(w0 - h0, w1 - h1);
        if (is3) { g_W3hi[id] = hp; g_W3lo[id] = lp; }
        else     { g_W2hi[id] = hp; g_W2lo[id] = lp; }
    }
}

// ---------------- persistent MLP kernel: 256 threads, 128 points per tile ----------------
__global__ __launch_bounds__(256, 2)
void mlp_kernel(const float* __restrict__ x, const float* __restrict__ nd,
                const float* __restrict__ W1, const float* __restrict__ b1,
                const float* __restrict__ b2, const float* __restrict__ b3,
                const float* __restrict__ W4, const float* __restrict__ b4)
{
    extern __shared__ char smraw[];
    float* Hs = (float*)(smraw + SM_HS);
    uint4* W2FH = (uint4*)(smraw + SM_W2FH);
    uint4* W2FL = (uint4*)(smraw + SM_W2FL);
    float* mf = (float*)(smraw + SM_MISC);

    const int tid = threadIdx.x;
    const int lane = tid & 31, warp = tid >> 5;
    const int g = lane >> 2, t = lane & 3;
    const int n0 = warp * 16;              // each warp owns 16 points (2 n-tiles of 8)

    // ---- phase 0: stage W2 fragments (copy, already packed) + small params ----
    {
        const uint4* srcH = (const uint4*)g_W2hi;
        const uint4* srcL = (const uint4*)g_W2lo;
        for (int i = tid; i < NW2 / 4; i += 256) { W2FH[i] = srcH[i]; W2FL[i] = srcL[i]; }
        for (int i = tid; i < 200; i += 256) mf[i] = W1[i];
        if (tid < 100) { mf[200 + tid] = b1[tid]; mf[300 + tid] = b2[tid]; }
        if (tid < 32)  mf[400 + tid] = (tid < 30) ? b3[tid] : 0.f;
        if (tid < 60)  mf[432 + tid] = W4[tid];
        if (tid < 2)   mf[492 + tid] = b4[tid];
    }
    __syncthreads();

    const uint4* W3h4 = (const uint4*)g_W3hi;
    const uint4* W3l4 = (const uint4*)g_W3lo;

    for (int tile = blockIdx.x; tile < NTILES; tile += GRID_MLP) {
        const int pbase = tile * 128;

        // ---- layer 1: 2 -> 100, ReLU. Two threads per point (j-halves). ----
        {
            const int p = tid & 127, half = tid >> 7;
            const int pg = pbase + p;
            float px = 0.f, py = 0.f;
            if (pg < TOTAL) {
                const float2 v = (pg < BN) ? ((const float2*)x)[pg]
                                           : ((const float2*)nd)[pg - BN];
                px = v.x; py = v.y;
            }
            const int j0 = half * 50;
            #pragma unroll 10
            for (int j = j0; j < j0 + 50; j++) {
                float v = fmaf(mf[2 * j], px, fmaf(mf[2 * j + 1], py, mf[200 + j]));
                Hs[j * NSTR + p] = fmaxf(v, 0.f);
            }
            for (int i = tid; i < 12 * NSTR; i += 256) Hs[100 * NSTR + i] = 0.f;
        }
        __syncthreads();

        // ---- layer 2: 100 -> 100 via bf16 split-2 mma (3 products), A-frags from SMEM ----
        float C[MT2][2][4];
        #pragma unroll
        for (int mt = 0; mt < MT2; mt++)
            #pragma unroll
            for (int nt = 0; nt < 2; nt++)
                #pragma unroll
                for (int r = 0; r < 4; r++) C[mt][nt][r] = 0.f;

        for (int kt = 0; kt < KT; kt++) {
            const int k0 = kt * 16 + 2 * t;
            unsigned bh[2][2], bl[2][2];
            #pragma unroll
            for (int nt = 0; nt < 2; nt++) {
                const int c = n0 + nt * 8 + g;
                const float r0 = Hs[(k0 + 0) * NSTR + c];
                const float r1 = Hs[(k0 + 1) * NSTR + c];
                const float r2 = Hs[(k0 + 8) * NSTR + c];
                const float r3 = Hs[(k0 + 9) * NSTR + c];
                bh[nt][0] = bf2(r0, r1);
                bh[nt][1] = bf2(r2, r3);
                bl[nt][0] = bf2(r0 - blo(bh[nt][0]), r1 - bhi(bh[nt][0]));
                bl[nt][1] = bf2(r2 - blo(bh[nt][1]), r3 - bhi(bh[nt][1]));
            }
            #pragma unroll
            for (int mt = 0; mt < MT2; mt++) {
                const int base = (kt * MT2 + mt) * 32 + lane;
                const uint4 ah = W2FH[base];
                const uint4 al = W2FL[base];
                #pragma unroll
                for (int nt = 0; nt < 2; nt++) {
                    mma16(C[mt][nt], ah, bh[nt][0], bh[nt][1]);
                    mma16(C[mt][nt], ah, bl[nt][0], bl[nt][1]);
                    mma16(C[mt][nt], al, bh[nt][0], bh[nt][1]);
                }
            }
        }
        __syncthreads();   // all layer-2 reads of Hs complete

        // write h2 = relu(C + b2) into Hs rows 0..111 (rows >=100 zeroed)
        #pragma unroll
        for (int mt = 0; mt < MT2; mt++)
            #pragma unroll
            for (int half = 0; half < 2; half++) {
                const int row = mt * 16 + g + half * 8;
                const float bias = (row < 100) ? mf[300 + row] : 0.f;
                #pragma unroll
                for (int nt = 0; nt < 2; nt++) {
                    float v0 = C[mt][nt][2 * half + 0] + bias;
                    float v1 = C[mt][nt][2 * half + 1] + bias;
                    if (row >= 100) { v0 = 0.f; v1 = 0.f; }
                    else { v0 = fmaxf(v0, 0.f); v1 = fmaxf(v1, 0.f); }
                    Hs[row * NSTR + n0 + nt * 8 + 2 * t] = v0;
                    Hs[row * NSTR + n0 + nt * 8 + 2 * t + 1] = v1;
                }
            }
        __syncthreads();

        // ---- layer 3: 100 -> 30 via bf16 split-2 mma (W3 frags from L2) ----
        float D[MT3][2][4];
        #pragma unroll
        for (int mt = 0; mt < MT3; mt++)
            #pragma unroll
            for (int nt = 0; nt < 2; nt++)
                #pragma unroll
                for (int r = 0; r < 4; r++) D[mt][nt][r] = 0.f;

        for (int kt = 0; kt < KT; kt++) {
            uint4 ah[MT3], al[MT3];
            #pragma unroll
            for (int mt = 0; mt < MT3; mt++) {
                const int base = (kt * MT3 + mt) * 32 + lane;
                ah[mt] = W3h4[base];
                al[mt] = W3l4[base];
            }
            const int k0 = kt * 16 + 2 * t;
            unsigned bh[2][2], bl[2][2];
            #pragma unroll
            for (int nt = 0; nt < 2; nt++) {
                const int c = n0 + nt * 8 + g;
                const float r0 = Hs[(k0 + 0) * NSTR + c];
                const float r1 = Hs[(k0 + 1) * NSTR + c];
                const float r2 = Hs[(k0 + 8) * NSTR + c];
                const float r3 = Hs[(k0 + 9) * NSTR + c];
                bh[nt][0] = bf2(r0, r1);
                bh[nt][1] = bf2(r2, r3);
                bl[nt][0] = bf2(r0 - blo(bh[nt][0]), r1 - bhi(bh[nt][0]));
                bl[nt][1] = bf2(r2 - blo(bh[nt][1]), r3 - bhi(bh[nt][1]));
            }
            #pragma unroll
            for (int mt = 0; mt < MT3; mt++)
                #pragma unroll
                for (int nt = 0; nt < 2; nt++) {
                    mma16(D[mt][nt], ah[mt], bh[nt][0], bh[nt][1]);
                    mma16(D[mt][nt], ah[mt], bl[nt][0], bl[nt][1]);
                    mma16(D[mt][nt], al[mt], bh[nt][0], bh[nt][1]);
                }
        }

        // ---- layer 4: 30 -> 2 directly from D fragments (no smem round-trip) ----
        // Thread holds rows {mt*16+g, mt*16+g+8} x cols {2t, 2t+1} per nt for its 2 points.
        // Reduce over rows within the t-group (lanes g=0..7, xor 4/8/16).
        {
            float acc[2][2][2];   // [nt][col01][out01]
            #pragma unroll
            for (int nt = 0; nt < 2; nt++)
                #pragma unroll
                for (int cc2 = 0; cc2 < 2; cc2++) { acc[nt][cc2][0] = 0.f; acc[nt][cc2][1] = 0.f; }
            #pragma unroll
            for (int mt = 0; mt < MT3; mt++)
                #pragma unroll
                for (int half = 0; half < 2; half++) {
                    const int row = mt * 16 + g + half * 8;
                    const float w0 = (row < 30) ? mf[432 + row] : 0.f;   // W4[0][row]
                    const float w1 = (row < 30) ? mf[462 + row] : 0.f;   // W4[1][row]
                    const float bias = (row < 30) ? mf[400 + row] : 0.f;
                    #pragma unroll
                    for (int nt = 0; nt < 2; nt++) {
                        const float h0 = fmaxf(D[mt][nt][2 * half + 0] + bias, 0.f);
                        const float h1 = fmaxf(D[mt][nt][2 * half + 1] + bias, 0.f);
                        acc[nt][0][0] = fmaf(w0, h0, acc[nt][0][0]);
                        acc[nt][0][1] = fmaf(w1, h0, acc[nt][0][1]);
                        acc[nt][1][0] = fmaf(w0, h1, acc[nt][1][0]);
                        acc[nt][1][1] = fmaf(w1, h1, acc[nt][1][1]);
                    }
                }
            // reduce across g (lanes xor 4, 8, 16 share the same point columns)
            #pragma unroll
            for (int o = 4; o <= 16; o <<= 1)
                #pragma unroll
                for (int nt = 0; nt < 2; nt++)
                    #pragma unroll
                    for (int cc2 = 0; cc2 < 2; cc2++) {
                        acc[nt][cc2][0] += __shfl_xor_sync(0xffffffffu, acc[nt][cc2][0], o);
                        acc[nt][cc2][1] += __shfl_xor_sync(0xffffffffu, acc[nt][cc2][1], o);
                    }
            if (g == 0) {   // lanes 0..3 hold final sums for their 4 point-columns
                #pragma unroll
                for (int nt = 0; nt < 2; nt++)
                    #pragma unroll
                    for (int cc2 = 0; cc2 < 2; cc2++) {
                        const int pg = pbase + n0 + nt * 8 + 2 * t + cc2;
                        if (pg < TOTAL)
                            ((float2*)g_feat)[pg] = make_float2(acc[nt][cc2][0] + mf[492],
                                                                acc[nt][cc2][1] + mf[493]);
                    }
            }
        }
        __syncthreads();   // Hs reads (layer 3) done before next tile's layer-1 writes
    }
}

// ---------------- routing kernel: one block per query b ----------------
__global__ __launch_bounds__(256)
void route_kernel(const int* __restrict__ nbr_idx, const int* __restrict__ labels,
                  float* __restrict__ out)
{
    __shared__ float p_s[CC];
    __shared__ float terms[DD - 1];

    const int b = blockIdx.x;
    const int tid = threadIdx.x;
    const int d = tid >> 5, lane = tid & 31;

    if (tid < CC) p_s[tid] = 0.f;
    __syncthreads();

    const float2 q = ((const float2*)g_feat)[b];
    const int idx = nbr_idx[b * (DD * KK) + tid];
    const float2 g = ((const float2*)g_feat)[BN + idx];

    const float dx = g.x - q.x + 1e-6f;
    const float dy = g.y - q.y + 1e-6f;
    const float neg = -sqrtf(fmaf(dx, dx, dy * dy));

    float m = neg;
    #pragma unroll
    for (int o = 16; o > 0; o >>= 1) m = fmaxf(m, __shfl_xor_sync(0xffffffffu, m, o));
    const float e = __expf(neg - m);
    float s = e;
    #pragma unroll
    for (int o = 16; o > 0; o >>= 1) s += __shfl_xor_sync(0xffffffffu, s, o);

    if (d < DD - 1) {
        if (lane == 0) terms[d] = __logf(__fdividef(1.0f, s) + 1e-4f);
    } else {
        const int c = labels[idx];
        atomicAdd(&p_s[c], __fdividef(e, s));
    }
    __syncthreads();

    if (tid < CC) {
        float tsum = terms[0] + terms[1] + terms[2] + terms[3] + terms[4] + terms[5] + terms[6];
        out[(long)b * CC + tid] = __logf(p_s[tid] + 1e-4f) + tsum;
    }
}

extern "C" void kernel_launch(void* const* d_in, const int* in_sizes, int n_in,
                              void* d_out, int out_size)
{
    const float* x      = (const float*)d_in[0];
    const float* nd     = (const float*)d_in[1];
    const float* W1     = (const float*)d_in[2];
    const float* b1     = (const float*)d_in[3];
    const float* W2     = (const float*)d_in[4];
    const float* b2     = (const float*)d_in[5];
    const float* W3     = (const float*)d_in[6];
    const float* b3     = (const float*)d_in[7];
    const float* W4     = (const float*)d_in[8];
    const float* b4     = (const float*)d_in[9];
    const int*   labels = (const int*)d_in[10];
    const int*   nbr    = (const int*)d_in[11];
    float* out = (float*)d_out;

    cudaFuncSetAttribute(mlp_kernel, cudaFuncAttributeMaxDynamicSharedMemorySize, SMEM_TOTAL);

    pack_kernel<<<64, 256>>>(W2, W3);
    mlp_kernel<<<GRID_MLP, 256, SMEM_TOTAL>>>(x, nd, W1, b1, b2, b3, W4, b4);
    route_kernel<<<BN, 256>>>(nbr, labels, out);
}